// round 8
// baseline (speedup 1.0000x reference)
#include <cuda_runtime.h>
#include <cstdint>

// ============================================================================
// Y[500000,256] = X @ W via mma.sync tf32 (tcgen05 unavailable at plain sm_103
// PTX target).
//
// R7 design: quarter-N CTAs for 2-CTA/SM occupancy + minimal smem traffic.
//  - 296 CTAs (148 SM x 2). CTA quad (4h+q) covers one 128-row tile group x
//    64-col N-slice. X rows read once per quad via L2.
//  - smem/CTA = 96KB: B frags 64KB (persistent) + 2x16KB A stages (K_CHUNK=32).
//  - 8 warps, 4mg x 2ng, warp tile 32x32, acc 32 regs. LDS per output row
//    drops 6KB -> 4KB vs R6.
//  - Producer: 4-rows-per-warp fully-coalesced LDG.128 (4 lines/inst),
//    cvt.rna.tf32, conflict-free STS.128 into fragment layout
//    [mt][ks][reg][lane].
//  - W prebuilt dense (g_Wt[n][k], tf32) by two tiny kernels; GEMM CTAs pack
//    their 64KB B-slice into fragment order once.
//  - Epilogue: streaming st.global.cs.v2.
// ============================================================================

#define D_DIM    256
#define N_Q      64
#define M_TILE   128
#define K_CHUNK  32
#define NCHUNKS  8
#define NROWS_T  500000L
#define NTILES_T 3907        // ceil(500000/128)
#define NQUADS   74
#define NCTA     296
#define NTHREADS 256

// smem layout (bytes):
//  B frags [8 nt][32 ksg][32 lane][2 f32]              = 65536
//  A frags 2 stages x [8 mt][4 ks][4 reg][32 lane] f32 = 32768
#define SB_B       0
#define SB_A       65536
#define A_STAGE_B  16384
#define SMEM_TOTAL (SB_A + 2 * A_STAGE_B)   // 98304 -> 2 CTAs/SM

__device__ __align__(16) float g_Wt[D_DIM * D_DIM];  // g_Wt[n*256+k] = W[k][n] (tf32)

// ---------------------------------------------------------------------------
__device__ __forceinline__ uint32_t smem_u32(const void* p) {
    uint32_t a;
    asm("{ .reg .u64 t; cvta.to.shared.u64 t, %1; cvt.u32.u64 %0, t; }"
        : "=r"(a) : "l"(p));
    return a;
}
__device__ __forceinline__ float to_tf32(float x) {
    float r; asm("cvt.rna.tf32.f32 %0, %1;" : "=f"(r) : "f"(x)); return r;
}
__device__ __forceinline__ void sts128(uint32_t a, float x, float y, float z, float w) {
    asm volatile("st.shared.v4.f32 [%0], {%1,%2,%3,%4};"
                 :: "r"(a), "f"(x), "f"(y), "f"(z), "f"(w) : "memory");
}
__device__ __forceinline__ void sts64(uint32_t a, float x, float y) {
    asm volatile("st.shared.v2.f32 [%0], {%1,%2};"
                 :: "r"(a), "f"(x), "f"(y) : "memory");
}
__device__ __forceinline__ uint32_t lds32(uint32_t a) {
    uint32_t v;
    asm volatile("ld.shared.b32 %0, [%1];" : "=r"(v) : "r"(a));
    return v;
}
__device__ __forceinline__ uint2 lds64(uint32_t a) {
    uint2 v;
    asm volatile("ld.shared.v2.b32 {%0,%1}, [%2];" : "=r"(v.x), "=r"(v.y) : "r"(a));
    return v;
}
__device__ __forceinline__ void stg64_cs(float* p, float a, float b) {
    asm volatile("st.global.cs.v2.f32 [%0], {%1,%2};"
                 :: "l"(p), "f"(a), "f"(b) : "memory");
}
// D = A(16x8,row) * B(8x8,col) + D, tf32 inputs (pre-rounded), f32 accum
__device__ __forceinline__ void mma_tf32(float* c, uint4 a, uint2 b) {
    asm volatile(
        "mma.sync.aligned.m16n8k8.row.col.f32.tf32.tf32.f32 "
        "{%0,%1,%2,%3}, {%4,%5,%6,%7}, {%8,%9}, {%0,%1,%2,%3};"
        : "+f"(c[0]), "+f"(c[1]), "+f"(c[2]), "+f"(c[3])
        : "r"(a.x), "r"(a.y), "r"(a.z), "r"(a.w), "r"(b.x), "r"(b.y));
}

// ---------------------------------------------------------------------------
// W build
// ---------------------------------------------------------------------------
__global__ void build_zero_kernel() {
    g_Wt[blockIdx.x * 256 + threadIdx.x] = 0.0f;
}
__global__ void build_scatter_kernel(const float* __restrict__ w,
                                     const int* __restrict__ rows,
                                     const int* __restrict__ cols, int nnz) {
    int i = blockIdx.x * 256 + threadIdx.x;
    if (i < nnz) g_Wt[cols[i] * D_DIM + rows[i]] = to_tf32(w[i]);
}

// ---------------------------------------------------------------------------
// Persistent GEMM
// ---------------------------------------------------------------------------
__global__ void __launch_bounds__(NTHREADS, 2)
dag_gemm_kernel(const float* __restrict__ X, float* __restrict__ Y) {
    extern __shared__ char smem[];
    const uint32_t sb = smem_u32(smem);
    const int tid  = threadIdx.x;
    const int w    = tid >> 5;
    const int lane = tid & 31;
    const int g    = lane >> 2;      // groupID
    const int tig  = lane & 3;       // thread-in-group
    const int cta  = blockIdx.x;
    const int h    = cta & 3;        // N quarter (64 cols)
    const int quad = cta >> 2;       // row-tile group
    const int ntiles = (NTILES_T - quad + NQUADS - 1) / NQUADS;

    // ---- pack B-slice [64 n x 256 k] into fragment order (once) ---------
    // B_frag[nt(8)][ksg(32)][lane(32)][j(2)] f32:
    //   n = h*64 + nt*8 + (lane>>2), k = ksg*8 + (lane&3) + j*4
    for (int i = 0; i < 32; i++) {
        int fid = tid + (i << 8);          // 0..8191
        int ln  = fid & 31;
        int ksg = (fid >> 5) & 31;
        int nt  = fid >> 10;               // 0..7
        int n   = h * N_Q + nt * 8 + (ln >> 2);
        int k0  = ksg * 8 + (ln & 3);
        sts64(sb + SB_B + (uint32_t)fid * 8,
              g_Wt[n * D_DIM + k0], g_Wt[n * D_DIM + k0 + 4]);
    }

    // producer mapping: thread t covers rows (t>>3)+32i (i=0..3), 128B k-seg
    const int pr0 = tid >> 3;            // 0..31
    const int k4  = tid & 7;             // float4 index within 32-k chunk
    const int nchunks = ntiles * NCHUNKS;

    // warp tiling: 4 m-groups x 2 n-groups, warp tile 32x32
    const int mtg0 = (w & 3) * 2;        // first of 2 mtiles (of 8)
    const int ng   = (w >> 2);           // 0..1
    float acc[2][4][4];
    #pragma unroll
    for (int mt = 0; mt < 2; mt++)
        #pragma unroll
        for (int nt = 0; nt < 4; nt++)
            #pragma unroll
            for (int q = 0; q < 4; q++) acc[mt][nt][q] = 0.0f;

    // A-frag STS.128 addresses, layout [mt(8)][ks(4)][reg(4)][lane(32)] f32.
    // float4 i: row = pr0+32i, k0 = k4*4: ks = k4>>1, regbit1 = k4&1,
    // reg = (rl>>3) | ((k4&1)<<1), lanes l0..l0+3 = (rl&7)*4..
    uint32_t a_sts[4];
    #pragma unroll
    for (int i = 0; i < 4; i++) {
        int row = pr0 + 32 * i;
        int rl  = row & 15, mt = row >> 4;
        int reg = (rl >> 3) | ((k4 & 1) << 1);
        int l0  = (rl & 7) << 2;
        a_sts[i] = (uint32_t)(((((mt * 4 + (k4 >> 1)) * 4 + reg) * 32) + l0) * 4);
    }

    __syncthreads();   // B frags ready

    float4 v[4];
    // ---- prologue: load+convert+store chunk 0 ---------------------------
    {
        long m0 = (long)quad * M_TILE;
        #pragma unroll
        for (int i = 0; i < 4; i++) {
            long grow = m0 + pr0 + 32 * i;
            v[i] = (grow < NROWS_T)
                 ? *reinterpret_cast<const float4*>(X + grow * D_DIM + k4 * 4)
                 : make_float4(0.f, 0.f, 0.f, 0.f);
        }
        uint32_t ab = sb + SB_A;
        #pragma unroll
        for (int i = 0; i < 4; i++)
            sts128(ab + a_sts[i], to_tf32(v[i].x), to_tf32(v[i].y),
                                  to_tf32(v[i].z), to_tf32(v[i].w));
    }

    for (int cg = 0; cg < nchunks; cg++) {
        __syncthreads();   // chunk cg resident in buffer cg&1

        const int j  = cg >> 3;            // tile
        const int ch = cg & 7;             // k-chunk (32 wide)
        const long m0 = (long)(quad + (long)j * NQUADS) * M_TILE;

        // prefetch next chunk into registers
        if (cg + 1 < nchunks) {
            const int jn  = (cg + 1) >> 3;
            const int chn = (cg + 1) & 7;
            long m0n = (long)(quad + (long)jn * NQUADS) * M_TILE;
            #pragma unroll
            for (int i = 0; i < 4; i++) {
                long grow = m0n + pr0 + 32 * i;
                v[i] = (grow < NROWS_T)
                     ? *reinterpret_cast<const float4*>(
                           X + grow * D_DIM + chn * K_CHUNK + k4 * 4)
                     : make_float4(0.f, 0.f, 0.f, 0.f);
            }
        }

        // ---- compute chunk from smem buffer -----------------------------
        {
            const uint32_t ab = sb + SB_A + (uint32_t)(cg & 1) * A_STAGE_B;
            const uint32_t bb = sb + SB_B;
            #pragma unroll
            for (int ks = 0; ks < 4; ks++) {
                const int ksg = ch * 4 + ks;
                uint4 a0, a1;
                {
                    uint32_t base0 = ab + (uint32_t)(((mtg0 * 4 + ks) * 4) * 128)
                                        + (uint32_t)lane * 4;
                    a0.x = lds32(base0);
                    a0.y = lds32(base0 + 128);
                    a0.z = lds32(base0 + 256);
                    a0.w = lds32(base0 + 384);
                    uint32_t base1 = base0 + (uint32_t)(4 * 4 * 128);
                    a1.x = lds32(base1);
                    a1.y = lds32(base1 + 128);
                    a1.z = lds32(base1 + 256);
                    a1.w = lds32(base1 + 384);
                }
                uint2 bfr[4];
                #pragma unroll
                for (int nt = 0; nt < 4; nt++)
                    bfr[nt] = lds64(bb + (uint32_t)((((ng * 4 + nt) * 32 + ksg) * 32
                                                    + lane) * 8));
                #pragma unroll
                for (int nt = 0; nt < 4; nt++) {
                    mma_tf32(acc[0][nt], a0, bfr[nt]);
                    mma_tf32(acc[1][nt], a1, bfr[nt]);
                }
            }
        }

        // ---- epilogue on last chunk of tile -----------------------------
        if (ch == 7) {
            const long mw = m0 + (long)(w & 3) * 32;
            const int  nb = h * N_Q + ng * 32;
            #pragma unroll
            for (int mt = 0; mt < 2; mt++) {
                long r0 = mw + mt * 16 + g;
                long r1 = r0 + 8;
                #pragma unroll
                for (int nt = 0; nt < 4; nt++) {
                    int c0 = nb + nt * 8 + tig * 2;
                    if (r0 < NROWS_T)
                        stg64_cs(Y + r0 * D_DIM + c0, acc[mt][nt][0], acc[mt][nt][1]);
                    if (r1 < NROWS_T)
                        stg64_cs(Y + r1 * D_DIM + c0, acc[mt][nt][2], acc[mt][nt][3]);
                    #pragma unroll
                    for (int q = 0; q < 4; q++) acc[mt][nt][q] = 0.0f;
                }
            }
        }

        // ---- convert + store prefetched chunk into other buffer ---------
        if (cg + 1 < nchunks) {
            uint32_t ab = sb + SB_A + (uint32_t)((cg + 1) & 1) * A_STAGE_B;
            #pragma unroll
            for (int i = 0; i < 4; i++)
                sts128(ab + a_sts[i], to_tf32(v[i].x), to_tf32(v[i].y),
                                      to_tf32(v[i].z), to_tf32(v[i].w));
        }
    }
}

// ---------------------------------------------------------------------------
extern "C" void kernel_launch(void* const* d_in, const int* in_sizes, int n_in,
                              void* d_out, int out_size) {
    const float* X    = (const float*)d_in[0];
    const float* wv   = (const float*)d_in[1];
    const int*   rows = (const int*)d_in[2];
    const int*   cols = (const int*)d_in[3];
    const int nnz = in_sizes[1];

    build_zero_kernel<<<D_DIM * D_DIM / 256, 256>>>();
    build_scatter_kernel<<<(nnz + 255) / 256, 256>>>(wv, rows, cols, nnz);

    cudaFuncSetAttribute(dag_gemm_kernel,
                         cudaFuncAttributeMaxDynamicSharedMemorySize, SMEM_TOTAL);
    dag_gemm_kernel<<<NCTA, NTHREADS, SMEM_TOTAL>>>(X, (float*)d_out);
}

// round 9
// speedup vs baseline: 1.5332x; 1.5332x over previous
#include <cuda_runtime.h>
#include <cuda_fp16.h>
#include <cstdint>

// ============================================================================
// Y[500000,256] = X @ W via mma.sync f16 m16n8k16 (f32 accum).
// R8: switch tf32-k8 -> f16-k16: halves mma count AND halves smem bytes.
// Precision: x,W rounded RN to f16, products zero-mean err ~4e-4, f32 accum.
//
// Structure = R6 winner: fused kernel (B packed to f16 frag order from
// w/rows/cols), 152 CTAs in N-half pairs (X L2 reuse), 8 warps 4mg x 2ng
// (warp tile 32x64), K_CHUNK=64 double-buffered A in fragment layout,
// conflict-free STS.64/LDS, streaming Y stores.
// ============================================================================

#define D_DIM    256
#define N_HALF   128
#define M_TILE   128
#define K_CHUNK  64
#define NCHUNKS  4
#define NROWS_T  500000L
#define NTILES_T 3907        // ceil(500000/128)
#define NPAIRS   76
#define NCTA     152
#define NTHREADS 256

// smem layout (bytes):
//  B frags [16 nt][16 ksg][32 lane][2 reg] f16x2 = 65536
//  A frags 2 stages x [8 mt][4 ks][4 reg][32 lane] f16x2 = 32768
#define SB_B       0
#define SB_A       65536
#define A_STAGE_B  16384
#define SMEM_TOTAL (SB_A + 2 * A_STAGE_B)   // 98304

// ---------------------------------------------------------------------------
__device__ __forceinline__ uint32_t smem_u32(const void* p) {
    uint32_t a;
    asm("{ .reg .u64 t; cvta.to.shared.u64 t, %1; cvt.u32.u64 %0, t; }"
        : "=r"(a) : "l"(p));
    return a;
}
__device__ __forceinline__ void sts128(uint32_t a, uint32_t x, uint32_t y,
                                       uint32_t z, uint32_t w) {
    asm volatile("st.shared.v4.b32 [%0], {%1,%2,%3,%4};"
                 :: "r"(a), "r"(x), "r"(y), "r"(z), "r"(w) : "memory");
}
__device__ __forceinline__ void sts64(uint32_t a, uint32_t x, uint32_t y) {
    asm volatile("st.shared.v2.b32 [%0], {%1,%2};"
                 :: "r"(a), "r"(x), "r"(y) : "memory");
}
__device__ __forceinline__ void sts16(uint32_t a, uint16_t v) {
    asm volatile("st.shared.u16 [%0], %1;" :: "r"(a), "h"(v) : "memory");
}
__device__ __forceinline__ uint32_t lds32(uint32_t a) {
    uint32_t v;
    asm volatile("ld.shared.b32 %0, [%1];" : "=r"(v) : "r"(a));
    return v;
}
__device__ __forceinline__ uint2 lds64(uint32_t a) {
    uint2 v;
    asm volatile("ld.shared.v2.b32 {%0,%1}, [%2];" : "=r"(v.x), "=r"(v.y) : "r"(a));
    return v;
}
__device__ __forceinline__ void stg64_cs(float* p, float a, float b) {
    asm volatile("st.global.cs.v2.f32 [%0], {%1,%2};"
                 :: "l"(p), "f"(a), "f"(b) : "memory");
}
__device__ __forceinline__ uint32_t pack_h2(float a, float b) {
    __half2 h = __floats2half2_rn(a, b);     // a -> low, b -> high
    return *reinterpret_cast<uint32_t*>(&h);
}
// D(16x8,f32) += A(16x16,f16,row) * B(16x8,f16,col)
__device__ __forceinline__ void mma_f16(float* c, uint4 a, uint2 b) {
    asm volatile(
        "mma.sync.aligned.m16n8k16.row.col.f32.f16.f16.f32 "
        "{%0,%1,%2,%3}, {%4,%5,%6,%7}, {%8,%9}, {%0,%1,%2,%3};"
        : "+f"(c[0]), "+f"(c[1]), "+f"(c[2]), "+f"(c[3])
        : "r"(a.x), "r"(a.y), "r"(a.z), "r"(a.w), "r"(b.x), "r"(b.y));
}

// ---------------------------------------------------------------------------
// Fused build + persistent GEMM
// ---------------------------------------------------------------------------
__global__ void __launch_bounds__(NTHREADS, 1)
dag_gemm_kernel(const float* __restrict__ X,
                const float* __restrict__ wv,
                const int* __restrict__ rows,
                const int* __restrict__ cols,
                int nnz,
                float* __restrict__ Y) {
    extern __shared__ char smem[];
    const uint32_t sb = smem_u32(smem);
    const int tid  = threadIdx.x;
    const int w    = tid >> 5;
    const int lane = tid & 31;
    const int g    = lane >> 2;      // groupID
    const int tig  = lane & 3;       // thread-in-group
    const int cta  = blockIdx.x;
    const int h    = cta & 1;        // N-half
    const int pair = cta >> 1;
    const int ntiles = (NTILES_T - pair + NPAIRS - 1) / NPAIRS;

    // ---- build B-half f16 fragments in smem: zero, then scatter ----------
    // B_frag[nt(16)][ksg(16)][lane(32)][breg(2)] f16x2 (8B per lane entry):
    //   element (n,k): nt = nl>>3, gq = nl&7; ksg = k>>4, wi = k&15:
    //   breg = wi>>3, tg = (wi>>1)&3, lo = wi&1
    #pragma unroll
    for (int i = 0; i < 16; i++)
        sts128(sb + SB_B + (uint32_t)(tid + (i << 8)) * 16, 0u, 0u, 0u, 0u);
    __syncthreads();
    for (int i = tid; i < nnz; i += NTHREADS) {
        int nl = cols[i] - h * N_HALF;
        if ((unsigned)nl < (unsigned)N_HALF) {
            int k   = rows[i];
            int nt  = nl >> 3, gq = nl & 7;
            int ksg = k >> 4,  wi = k & 15;
            int br  = wi >> 3, tg = (wi >> 1) & 3, lo = wi & 1;
            uint32_t a = sb + SB_B
                       + (uint32_t)(((nt * 16 + ksg) * 32 + gq * 4 + tg) * 8
                                    + br * 4 + lo * 2);
            __half hv = __float2half_rn(wv[i]);
            sts16(a, *reinterpret_cast<uint16_t*>(&hv));
        }
    }

    // producer mapping: row r = tid>>1, col half hc = tid&1 (32 cols each)
    const int pr  = tid >> 1;
    const int hc  = tid & 1;
    const int nchunks = ntiles * NCHUNKS;

    // warp tiling: 4 m-groups x 2 n-groups, warp tile 32x64
    const int mtg0 = (w & 3) * 2;           // first of 2 mtiles (of 8)
    const int ng   = (w >> 2);              // 0..1
    float acc[2][8][4];
    #pragma unroll
    for (int mt = 0; mt < 2; mt++)
        #pragma unroll
        for (int nt = 0; nt < 8; nt++)
            #pragma unroll
            for (int q = 0; q < 4; q++) acc[mt][nt][q] = 0.0f;

    // A-frag STS.64 addresses, layout [mt(8)][ks(4)][reg(4)][lane(32)] f16x2.
    // float4 q (row pr, k0 = hc*32+4q..+3) -> 2 f16x2 at lanes lane0, lane0+1:
    //   ks = k0>>4, wi = k0&15, kh = wi>>3, tg0 = (wi>>1)&3 (even),
    //   reg = (rl>>3) + 2*kh, lane0 = (gq*4 + tg0) ^ (ks&2)  [bank de-conflict]
    uint32_t a_sts[8];
    {
        int mt = pr >> 4, rl = pr & 15;
        int gq = rl & 7,  rh = rl >> 3;
        #pragma unroll
        for (int q = 0; q < 8; q++) {
            int k0  = hc * 32 + q * 4;
            int ks  = k0 >> 4, wi = k0 & 15;
            int reg = rh + ((wi >> 3) << 1);
            int ln0 = (gq * 4 + ((wi >> 1) & 3)) ^ (ks & 2);
            a_sts[q] = (uint32_t)((((mt * 4 + ks) * 4 + reg) * 32 + ln0) * 4);
        }
    }

    __syncthreads();   // B frags ready

    uint2 u[8];
    // ---- prologue: load+convert chunk 0, store to stage 0 ----------------
    {
        long grow = (long)pair * M_TILE + pr;
        const float4* src = reinterpret_cast<const float4*>(
            X + grow * D_DIM + hc * 32);
        #pragma unroll
        for (int q = 0; q < 8; q++) {
            float4 v = (grow < NROWS_T) ? src[q] : make_float4(0.f, 0.f, 0.f, 0.f);
            u[q].x = pack_h2(v.x, v.y);
            u[q].y = pack_h2(v.z, v.w);
        }
        uint32_t ab = sb + SB_A;
        #pragma unroll
        for (int q = 0; q < 8; q++)
            sts64(ab + a_sts[q], u[q].x, u[q].y);
    }

    for (int cg = 0; cg < nchunks; cg++) {
        __syncthreads();   // chunk cg resident in buffer cg&1

        const int j  = cg >> 2;       // tile
        const int ch = cg & 3;        // k-chunk (64)
        const long m0 = (long)(pair + (long)j * NPAIRS) * M_TILE;

        // prefetch + convert next chunk into registers
        if (cg + 1 < nchunks) {
            const int jn  = (cg + 1) >> 2;
            const int chn = (cg + 1) & 3;
            long grow = (long)(pair + (long)jn * NPAIRS) * M_TILE + pr;
            const float4* src = reinterpret_cast<const float4*>(
                X + grow * D_DIM + chn * K_CHUNK + hc * 32);
            #pragma unroll
            for (int q = 0; q < 8; q++) {
                float4 v = (grow < NROWS_T) ? src[q]
                                            : make_float4(0.f, 0.f, 0.f, 0.f);
                u[q].x = pack_h2(v.x, v.y);
                u[q].y = pack_h2(v.z, v.w);
            }
        }

        // ---- compute chunk from smem buffer ------------------------------
        {
            const uint32_t ab = sb + SB_A + (uint32_t)(cg & 1) * A_STAGE_B;
            const uint32_t bb = sb + SB_B;
            #pragma unroll
            for (int ks = 0; ks < 4; ks++) {
                const int ksg = ch * 4 + ks;
                const uint32_t lx = (uint32_t)((lane ^ (ks & 2)) * 4);
                uint4 a0, a1;
                {
                    uint32_t base0 = ab + (uint32_t)((mtg0 * 4 + ks) * 512) + lx;
                    a0.x = lds32(base0);
                    a0.y = lds32(base0 + 128);
                    a0.z = lds32(base0 + 256);
                    a0.w = lds32(base0 + 384);
                    uint32_t base1 = base0 + 2048;   // next mt
                    a1.x = lds32(base1);
                    a1.y = lds32(base1 + 128);
                    a1.z = lds32(base1 + 256);
                    a1.w = lds32(base1 + 384);
                }
                uint2 bfr[8];
                #pragma unroll
                for (int nt = 0; nt < 8; nt++)
                    bfr[nt] = lds64(bb + (uint32_t)((((ng * 8 + nt) * 16 + ksg) * 32
                                                    + lane) * 8));
                #pragma unroll
                for (int nt = 0; nt < 8; nt++) {
                    mma_f16(acc[0][nt], a0, bfr[nt]);
                    mma_f16(acc[1][nt], a1, bfr[nt]);
                }
            }
        }

        // ---- epilogue on last chunk of tile ------------------------------
        if (ch == 3) {
            const long mw = m0 + (long)(w & 3) * 32;
            const int  nb = h * N_HALF + ng * 64;
            #pragma unroll
            for (int mt = 0; mt < 2; mt++) {
                long r0 = mw + mt * 16 + g;
                long r1 = r0 + 8;
                #pragma unroll
                for (int nt = 0; nt < 8; nt++) {
                    int c0 = nb + nt * 8 + tig * 2;
                    if (r0 < NROWS_T)
                        stg64_cs(Y + r0 * D_DIM + c0, acc[mt][nt][0], acc[mt][nt][1]);
                    if (r1 < NROWS_T)
                        stg64_cs(Y + r1 * D_DIM + c0, acc[mt][nt][2], acc[mt][nt][3]);
                    #pragma unroll
                    for (int q = 0; q < 4; q++) acc[mt][nt][q] = 0.0f;
                }
            }
        }

        // ---- store prefetched chunk into other buffer --------------------
        if (cg + 1 < nchunks) {
            uint32_t ab = sb + SB_A + (uint32_t)((cg + 1) & 1) * A_STAGE_B;
            #pragma unroll
            for (int q = 0; q < 8; q++)
                sts64(ab + a_sts[q], u[q].x, u[q].y);
        }
    }
}

// ---------------------------------------------------------------------------
extern "C" void kernel_launch(void* const* d_in, const int* in_sizes, int n_in,
                              void* d_out, int out_size) {
    const float* X    = (const float*)d_in[0];
    const float* wv   = (const float*)d_in[1];
    const int*   rows = (const int*)d_in[2];
    const int*   cols = (const int*)d_in[3];
    const int nnz = in_sizes[1];

    cudaFuncSetAttribute(dag_gemm_kernel,
                         cudaFuncAttributeMaxDynamicSharedMemorySize, SMEM_TOTAL);
    dag_gemm_kernel<<<NCTA, NTHREADS, SMEM_TOTAL>>>(X, wv, rows, cols, nnz,
                                                    (float*)d_out);
}

// round 10
// speedup vs baseline: 1.7795x; 1.1606x over previous
#include <cuda_runtime.h>
#include <cuda_fp16.h>
#include <cstdint>

// ============================================================================
// Y[500000,256] = X @ W via mma.sync f16 m16n8k16 (f32 accum).
// R9: occupancy fix. Same per-CTA structure as R8 (best: 595us), but
//  - __launch_bounds__(256, 2): cap regs at 128 so 2 CTAs fit per SM
//  - 296 CTAs (148 SM x 2, exactly one wave), NPAIRS=148
// => 16 warps/SM to hide LDS->mma latency, LDG bursts and barrier skew.
// ============================================================================

#define D_DIM    256
#define N_HALF   128
#define M_TILE   128
#define K_CHUNK  64
#define NCHUNKS  4
#define NROWS_T  500000L
#define NTILES_T 3907        // ceil(500000/128)
#define NPAIRS   148
#define NCTA     296
#define NTHREADS 256

// smem layout (bytes):
//  B frags [16 nt][16 ksg][32 lane][2 reg] f16x2 = 65536
//  A frags 2 stages x [8 mt][4 ks][4 reg][32 lane] f16x2 = 32768
#define SB_B       0
#define SB_A       65536
#define A_STAGE_B  16384
#define SMEM_TOTAL (SB_A + 2 * A_STAGE_B)   // 98304 -> 2 CTAs/SM

// ---------------------------------------------------------------------------
__device__ __forceinline__ uint32_t smem_u32(const void* p) {
    uint32_t a;
    asm("{ .reg .u64 t; cvta.to.shared.u64 t, %1; cvt.u32.u64 %0, t; }"
        : "=r"(a) : "l"(p));
    return a;
}
__device__ __forceinline__ void sts128(uint32_t a, uint32_t x, uint32_t y,
                                       uint32_t z, uint32_t w) {
    asm volatile("st.shared.v4.b32 [%0], {%1,%2,%3,%4};"
                 :: "r"(a), "r"(x), "r"(y), "r"(z), "r"(w) : "memory");
}
__device__ __forceinline__ void sts64(uint32_t a, uint32_t x, uint32_t y) {
    asm volatile("st.shared.v2.b32 [%0], {%1,%2};"
                 :: "r"(a), "r"(x), "r"(y) : "memory");
}
__device__ __forceinline__ void sts16(uint32_t a, uint16_t v) {
    asm volatile("st.shared.u16 [%0], %1;" :: "r"(a), "h"(v) : "memory");
}
__device__ __forceinline__ uint32_t lds32(uint32_t a) {
    uint32_t v;
    asm volatile("ld.shared.b32 %0, [%1];" : "=r"(v) : "r"(a));
    return v;
}
__device__ __forceinline__ uint2 lds64(uint32_t a) {
    uint2 v;
    asm volatile("ld.shared.v2.b32 {%0,%1}, [%2];" : "=r"(v.x), "=r"(v.y) : "r"(a));
    return v;
}
__device__ __forceinline__ void stg64_cs(float* p, float a, float b) {
    asm volatile("st.global.cs.v2.f32 [%0], {%1,%2};"
                 :: "l"(p), "f"(a), "f"(b) : "memory");
}
__device__ __forceinline__ uint32_t pack_h2(float a, float b) {
    __half2 h = __floats2half2_rn(a, b);     // a -> low, b -> high
    return *reinterpret_cast<uint32_t*>(&h);
}
// D(16x8,f32) += A(16x16,f16,row) * B(16x8,f16,col)
__device__ __forceinline__ void mma_f16(float* c, uint4 a, uint2 b) {
    asm volatile(
        "mma.sync.aligned.m16n8k16.row.col.f32.f16.f16.f32 "
        "{%0,%1,%2,%3}, {%4,%5,%6,%7}, {%8,%9}, {%0,%1,%2,%3};"
        : "+f"(c[0]), "+f"(c[1]), "+f"(c[2]), "+f"(c[3])
        : "r"(a.x), "r"(a.y), "r"(a.z), "r"(a.w), "r"(b.x), "r"(b.y));
}

// ---------------------------------------------------------------------------
// Fused build + persistent GEMM
// ---------------------------------------------------------------------------
__global__ void __launch_bounds__(NTHREADS, 2)
dag_gemm_kernel(const float* __restrict__ X,
                const float* __restrict__ wv,
                const int* __restrict__ rows,
                const int* __restrict__ cols,
                int nnz,
                float* __restrict__ Y) {
    extern __shared__ char smem[];
    const uint32_t sb = smem_u32(smem);
    const int tid  = threadIdx.x;
    const int w    = tid >> 5;
    const int lane = tid & 31;
    const int g    = lane >> 2;      // groupID
    const int tig  = lane & 3;       // thread-in-group
    const int cta  = blockIdx.x;
    const int h    = cta & 1;        // N-half
    const int pair = cta >> 1;
    const int ntiles = (NTILES_T - pair + NPAIRS - 1) / NPAIRS;

    // ---- build B-half f16 fragments in smem: zero, then scatter ----------
    // B_frag[nt(16)][ksg(16)][lane(32)][breg(2)] f16x2 (8B per lane entry):
    //   element (n,k): nt = nl>>3, gq = nl&7; ksg = k>>4, wi = k&15:
    //   breg = wi>>3, tg = (wi>>1)&3, lo = wi&1
    #pragma unroll
    for (int i = 0; i < 16; i++)
        sts128(sb + SB_B + (uint32_t)(tid + (i << 8)) * 16, 0u, 0u, 0u, 0u);
    __syncthreads();
    for (int i = tid; i < nnz; i += NTHREADS) {
        int nl = cols[i] - h * N_HALF;
        if ((unsigned)nl < (unsigned)N_HALF) {
            int k   = rows[i];
            int nt  = nl >> 3, gq = nl & 7;
            int ksg = k >> 4,  wi = k & 15;
            int br  = wi >> 3, tg = (wi >> 1) & 3, lo = wi & 1;
            uint32_t a = sb + SB_B
                       + (uint32_t)(((nt * 16 + ksg) * 32 + gq * 4 + tg) * 8
                                    + br * 4 + lo * 2);
            __half hv = __float2half_rn(wv[i]);
            sts16(a, *reinterpret_cast<uint16_t*>(&hv));
        }
    }

    // producer mapping: row r = tid>>1, col half hc = tid&1 (32 cols each)
    const int pr  = tid >> 1;
    const int hc  = tid & 1;
    const int nchunks = ntiles * NCHUNKS;

    // warp tiling: 4 m-groups x 2 n-groups, warp tile 32x64
    const int mtg0 = (w & 3) * 2;           // first of 2 mtiles (of 8)
    const int ng   = (w >> 2);              // 0..1
    float acc[2][8][4];
    #pragma unroll
    for (int mt = 0; mt < 2; mt++)
        #pragma unroll
        for (int nt = 0; nt < 8; nt++)
            #pragma unroll
            for (int q = 0; q < 4; q++) acc[mt][nt][q] = 0.0f;

    // A-frag STS.64 addresses, layout [mt(8)][ks(4)][reg(4)][lane(32)] f16x2.
    // float4 q (row pr, k0 = hc*32+4q..+3) -> 2 f16x2 at lanes lane0, lane0+1:
    //   ks = k0>>4, wi = k0&15, kh = wi>>3, tg0 = (wi>>1)&3 (even),
    //   reg = (rl>>3) + 2*kh, lane0 = (gq*4 + tg0) ^ (ks&2)  [bank de-conflict]
    uint32_t a_sts[8];
    {
        int rl = pr & 15, mt = pr >> 4;
        int gq = rl & 7,  rh = rl >> 3;
        #pragma unroll
        for (int q = 0; q < 8; q++) {
            int k0  = hc * 32 + q * 4;
            int ks  = k0 >> 4, wi = k0 & 15;
            int reg = rh + ((wi >> 3) << 1);
            int ln0 = (gq * 4 + ((wi >> 1) & 3)) ^ (ks & 2);
            a_sts[q] = (uint32_t)((((mt * 4 + ks) * 4 + reg) * 32 + ln0) * 4);
        }
    }

    __syncthreads();   // B frags ready

    uint2 u[8];
    // ---- prologue: load+convert chunk 0, store to stage 0 ----------------
    {
        long grow = (long)pair * M_TILE + pr;
        const float4* src = reinterpret_cast<const float4*>(
            X + grow * D_DIM + hc * 32);
        #pragma unroll
        for (int q = 0; q < 8; q++) {
            float4 v = (grow < NROWS_T) ? src[q] : make_float4(0.f, 0.f, 0.f, 0.f);
            u[q].x = pack_h2(v.x, v.y);
            u[q].y = pack_h2(v.z, v.w);
        }
        uint32_t ab = sb + SB_A;
        #pragma unroll
        for (int q = 0; q < 8; q++)
            sts64(ab + a_sts[q], u[q].x, u[q].y);
    }

    for (int cg = 0; cg < nchunks; cg++) {
        __syncthreads();   // chunk cg resident in buffer cg&1

        const int j  = cg >> 2;       // tile
        const int ch = cg & 3;        // k-chunk (64)
        const long m0 = (long)(pair + (long)j * NPAIRS) * M_TILE;

        // prefetch + convert next chunk into registers
        if (cg + 1 < nchunks) {
            const int jn  = (cg + 1) >> 2;
            const int chn = (cg + 1) & 3;
            long grow = (long)(pair + (long)jn * NPAIRS) * M_TILE + pr;
            const float4* src = reinterpret_cast<const float4*>(
                X + grow * D_DIM + chn * K_CHUNK + hc * 32);
            #pragma unroll
            for (int q = 0; q < 8; q++) {
                float4 v = (grow < NROWS_T) ? src[q]
                                            : make_float4(0.f, 0.f, 0.f, 0.f);
                u[q].x = pack_h2(v.x, v.y);
                u[q].y = pack_h2(v.z, v.w);
            }
        }

        // ---- compute chunk from smem buffer ------------------------------
        {
            const uint32_t ab = sb + SB_A + (uint32_t)(cg & 1) * A_STAGE_B;
            const uint32_t bb = sb + SB_B;
            #pragma unroll
            for (int ks = 0; ks < 4; ks++) {
                const int ksg = ch * 4 + ks;
                const uint32_t lx = (uint32_t)((lane ^ (ks & 2)) * 4);
                uint4 a0, a1;
                {
                    uint32_t base0 = ab + (uint32_t)((mtg0 * 4 + ks) * 512) + lx;
                    a0.x = lds32(base0);
                    a0.y = lds32(base0 + 128);
                    a0.z = lds32(base0 + 256);
                    a0.w = lds32(base0 + 384);
                    uint32_t base1 = base0 + 2048;   // next mt
                    a1.x = lds32(base1);
                    a1.y = lds32(base1 + 128);
                    a1.z = lds32(base1 + 256);
                    a1.w = lds32(base1 + 384);
                }
                uint2 bfr[8];
                #pragma unroll
                for (int nt = 0; nt < 8; nt++)
                    bfr[nt] = lds64(bb + (uint32_t)((((ng * 8 + nt) * 16 + ksg) * 32
                                                    + lane) * 8));
                #pragma unroll
                for (int nt = 0; nt < 8; nt++) {
                    mma_f16(acc[0][nt], a0, bfr[nt]);
                    mma_f16(acc[1][nt], a1, bfr[nt]);
                }
            }
        }

        // ---- epilogue on last chunk of tile ------------------------------
        if (ch == 3) {
            const long mw = m0 + (long)(w & 3) * 32;
            const int  nb = h * N_HALF + ng * 64;
            #pragma unroll
            for (int mt = 0; mt < 2; mt++) {
                long r0 = mw + mt * 16 + g;
                long r1 = r0 + 8;
                #pragma unroll
                for (int nt = 0; nt < 8; nt++) {
                    int c0 = nb + nt * 8 + tig * 2;
                    if (r0 < NROWS_T)
                        stg64_cs(Y + r0 * D_DIM + c0, acc[mt][nt][0], acc[mt][nt][1]);
                    if (r1 < NROWS_T)
                        stg64_cs(Y + r1 * D_DIM + c0, acc[mt][nt][2], acc[mt][nt][3]);
                    #pragma unroll
                    for (int q = 0; q < 4; q++) acc[mt][nt][q] = 0.0f;
                }
            }
        }

        // ---- store prefetched chunk into other buffer --------------------
        if (cg + 1 < nchunks) {
            uint32_t ab = sb + SB_A + (uint32_t)((cg + 1) & 1) * A_STAGE_B;
            #pragma unroll
            for (int q = 0; q < 8; q++)
                sts64(ab + a_sts[q], u[q].x, u[q].y);
        }
    }
}

// ---------------------------------------------------------------------------
extern "C" void kernel_launch(void* const* d_in, const int* in_sizes, int n_in,
                              void* d_out, int out_size) {
    const float* X    = (const float*)d_in[0];
    const float* wv   = (const float*)d_in[1];
    const int*   rows = (const int*)d_in[2];
    const int*   cols = (const int*)d_in[3];
    const int nnz = in_sizes[1];

    cudaFuncSetAttribute(dag_gemm_kernel,
                         cudaFuncAttributeMaxDynamicSharedMemorySize, SMEM_TOTAL);
    dag_gemm_kernel<<<NCTA, NTHREADS, SMEM_TOTAL>>>(X, wv, rows, cols, nnz,
                                                    (float*)d_out);
}

// round 12
// speedup vs baseline: 2.1097x; 1.1856x over previous
#include <cuda_runtime.h>
#include <cuda_fp16.h>
#include <cstdint>

// ============================================================================
// Y[500000,256] = X @ W via mma.sync f16 m16n8k16 (f32 accum).
// R10: l1tex wavefront reduction on top of R9 (512us):
//  - Coalesced LDG: each LDG.128 = 2 full rows x 256B contiguous (4 lines).
//    A-frag STS re-derived with (ks,hi) XOR lane swizzle.
//  - B-column permutation so each thread owns 16 contiguous Y cols ->
//    epilogue st.global.cs.v4 (halves store wavefronts).
//  - 296 CTAs, 2/SM, regs capped 128 (R9 proven).
// ============================================================================

#define D_DIM    256
#define N_HALF   128
#define M_TILE   128
#define K_CHUNK  64
#define NCHUNKS  4
#define NROWS_T  500000L
#define NTILES_T 3907        // ceil(500000/128)
#define NPAIRS   148
#define NCTA     296
#define NTHREADS 256

// smem layout (bytes):
//  B frags [16 nt][16 ksg][32 lane][2 reg] f16x2 = 65536
//  A frags 2 stages x [8 mt][4 ks][4 reg][32 lane] f16x2 = 32768
#define SB_B       0
#define SB_A       65536
#define A_STAGE_B  16384
#define SMEM_TOTAL (SB_A + 2 * A_STAGE_B)   // 98304 -> 2 CTAs/SM

// ---------------------------------------------------------------------------
__device__ __forceinline__ uint32_t smem_u32(const void* p) {
    uint32_t a;
    asm("{ .reg .u64 t; cvta.to.shared.u64 t, %1; cvt.u32.u64 %0, t; }"
        : "=r"(a) : "l"(p));
    return a;
}
__device__ __forceinline__ void sts128(uint32_t a, uint32_t x, uint32_t y,
                                       uint32_t z, uint32_t w) {
    asm volatile("st.shared.v4.b32 [%0], {%1,%2,%3,%4};"
                 :: "r"(a), "r"(x), "r"(y), "r"(z), "r"(w) : "memory");
}
__device__ __forceinline__ void sts64(uint32_t a, uint32_t x, uint32_t y) {
    asm volatile("st.shared.v2.b32 [%0], {%1,%2};"
                 :: "r"(a), "r"(x), "r"(y) : "memory");
}
__device__ __forceinline__ void sts16(uint32_t a, uint16_t v) {
    asm volatile("st.shared.u16 [%0], %1;" :: "r"(a), "h"(v) : "memory");
}
__device__ __forceinline__ uint32_t lds32(uint32_t a) {
    uint32_t v;
    asm volatile("ld.shared.b32 %0, [%1];" : "=r"(v) : "r"(a));
    return v;
}
__device__ __forceinline__ uint2 lds64(uint32_t a) {
    uint2 v;
    asm volatile("ld.shared.v2.b32 {%0,%1}, [%2];" : "=r"(v.x), "=r"(v.y) : "r"(a));
    return v;
}
__device__ __forceinline__ void stg128_cs(float* p, float a, float b,
                                          float c, float d) {
    asm volatile("st.global.cs.v4.f32 [%0], {%1,%2,%3,%4};"
                 :: "l"(p), "f"(a), "f"(b), "f"(c), "f"(d) : "memory");
}
__device__ __forceinline__ uint32_t pack_h2(float a, float b) {
    __half2 h = __floats2half2_rn(a, b);     // a -> low, b -> high
    return *reinterpret_cast<uint32_t*>(&h);
}
// D(16x8,f32) += A(16x16,f16,row) * B(16x8,f16,col)
__device__ __forceinline__ void mma_f16(float* c, uint4 a, uint2 b) {
    asm volatile(
        "mma.sync.aligned.m16n8k16.row.col.f32.f16.f16.f32 "
        "{%0,%1,%2,%3}, {%4,%5,%6,%7}, {%8,%9}, {%0,%1,%2,%3};"
        : "+f"(c[0]), "+f"(c[1]), "+f"(c[2]), "+f"(c[3])
        : "r"(a.x), "r"(a.y), "r"(a.z), "r"(a.w), "r"(b.x), "r"(b.y));
}

// ---------------------------------------------------------------------------
// Fused build + persistent GEMM
// ---------------------------------------------------------------------------
__global__ void __launch_bounds__(NTHREADS, 2)
dag_gemm_kernel(const float* __restrict__ X,
                const float* __restrict__ wv,
                const int* __restrict__ rows,
                const int* __restrict__ cols,
                int nnz,
                float* __restrict__ Y) {
    extern __shared__ char smem[];
    const uint32_t sb = smem_u32(smem);
    const int tid  = threadIdx.x;
    const int w    = tid >> 5;
    const int lane = tid & 31;
    const int g    = lane >> 2;      // groupID
    const int tig  = lane & 3;       // thread-in-group
    const int cta  = blockIdx.x;
    const int h    = cta & 1;        // N-half
    const int pair = cta >> 1;
    const int ntiles = (NTILES_T - pair + NPAIRS - 1) / NPAIRS;

    // ---- build B-half f16 fragments in smem: zero, then scatter ----------
    // B_frag[nt(16)][ksg(16)][lane(32)][breg(2)] f16x2.
    // Column PERMUTATION for v4 epilogue: within each 64-col ng-half,
    // Y col c maps to slot ((c&15)>>1)*8 + (c>>4)*2 + (c&1), so thread tig
    // ends up owning 16 contiguous Y columns tig*16..tig*16+15.
    #pragma unroll
    for (int i = 0; i < 16; i++)
        sts128(sb + SB_B + (uint32_t)(tid + (i << 8)) * 16, 0u, 0u, 0u, 0u);
    __syncthreads();
    for (int i = tid; i < nnz; i += NTHREADS) {
        int nl = cols[i] - h * N_HALF;
        if ((unsigned)nl < (unsigned)N_HALF) {
            int k    = rows[i];
            int ng_  = nl >> 6;
            int c    = nl & 63;
            int slot = (ng_ << 6) + ((c & 15) >> 1) * 8 + ((c >> 4) << 1) + (c & 1);
            int nt   = slot >> 3, gq = slot & 7;
            int ksg  = k >> 4,  wi = k & 15;
            int br   = wi >> 3, tg = (wi >> 1) & 3, lo = wi & 1;
            uint32_t a = sb + SB_B
                       + (uint32_t)(((nt * 16 + ksg) * 32 + gq * 4 + tg) * 8
                                    + br * 4 + lo * 2);
            __half hv = __float2half_rn(wv[i]);
            sts16(a, *reinterpret_cast<uint16_t*>(&hv));
        }
    }

    // ---- producer mapping (coalesced): inst i loads row w*8+i+64*hi,
    //      float4 at k4 (lane = hi*16 + k4) => 2 rows x 256B per warp inst.
    const int k4  = lane & 15;
    const int hi  = lane >> 4;
    const int nchunks = ntiles * NCHUNKS;

    // warp tiling: 4 m-groups x 2 n-groups, warp tile 32x64
    const int mtg0 = (w & 3) * 2;           // first of 2 mtiles (of 8)
    const int ng   = (w >> 2);              // 0..1
    float acc[2][8][4];
    #pragma unroll
    for (int mt = 0; mt < 2; mt++)
        #pragma unroll
        for (int nt = 0; nt < 8; nt++)
            #pragma unroll
            for (int q = 0; q < 4; q++) acc[mt][nt][q] = 0.0f;

    // A-frag STS addresses, layout [mt(8)][ks(4)][reg(4)][lane-slot(32)] f16x2
    // with lane swizzle slot = (gq*4 + lo1*2) ^ (ks<<2) ^ (hi<<4).
    //   row = w*8 + i + 64*hi: rl = (w&1)*8 + i -> gq = i, rh = w&1.
    //   k0 = k4*4: ks = k4>>2, lo1 = k4&1, l2h = (k4>>1)&1, reg = rh + 2*l2h.
    uint32_t a_sts[8];
    {
        const int ks  = k4 >> 2;
        const int lo1 = k4 & 1;
        const int l2h = (k4 >> 1) & 1;
        const int reg = (w & 1) + 2 * l2h;
        const int mt  = (w >> 1) + 4 * hi;
        #pragma unroll
        for (int i = 0; i < 8; i++) {
            int lnp = ((i * 4 + lo1 * 2) ^ (ks << 2)) ^ (hi << 4);
            a_sts[i] = (uint32_t)((((mt * 4 + ks) * 4 + reg) * 32 + lnp) * 4);
        }
    }

    __syncthreads();   // B frags ready

    uint2 u[8];
    // ---- prologue: load+convert chunk 0, store to stage 0 ----------------
    {
        long m0 = (long)pair * M_TILE;
        #pragma unroll
        for (int i = 0; i < 8; i++) {
            long grow = m0 + w * 8 + i + 64 * hi;
            float4 v = (grow < NROWS_T)
                ? *reinterpret_cast<const float4*>(X + grow * D_DIM + k4 * 4)
                : make_float4(0.f, 0.f, 0.f, 0.f);
            u[i].x = pack_h2(v.x, v.y);
            u[i].y = pack_h2(v.z, v.w);
        }
        uint32_t ab = sb + SB_A;
        #pragma unroll
        for (int i = 0; i < 8; i++)
            sts64(ab + a_sts[i], u[i].x, u[i].y);
    }

    for (int cg = 0; cg < nchunks; cg++) {
        __syncthreads();   // chunk cg resident in buffer cg&1

        const int j  = cg >> 2;       // tile
        const int ch = cg & 3;        // k-chunk (64)
        const long m0 = (long)(pair + (long)j * NPAIRS) * M_TILE;

        // prefetch + convert next chunk into registers (coalesced)
        if (cg + 1 < nchunks) {
            const int jn  = (cg + 1) >> 2;
            const int chn = (cg + 1) & 3;
            long m0n = (long)(pair + (long)jn * NPAIRS) * M_TILE;
            #pragma unroll
            for (int i = 0; i < 8; i++) {
                long grow = m0n + w * 8 + i + 64 * hi;
                float4 v = (grow < NROWS_T)
                    ? *reinterpret_cast<const float4*>(
                          X + grow * D_DIM + chn * K_CHUNK + k4 * 4)
                    : make_float4(0.f, 0.f, 0.f, 0.f);
                u[i].x = pack_h2(v.x, v.y);
                u[i].y = pack_h2(v.z, v.w);
            }
        }

        // ---- compute chunk from smem buffer ------------------------------
        {
            const uint32_t ab = sb + SB_A + (uint32_t)(cg & 1) * A_STAGE_B;
            const uint32_t bb = sb + SB_B;
            const uint32_t hswz = (uint32_t)(((mtg0 >> 2) & 1) << 4);
            #pragma unroll
            for (int ks = 0; ks < 4; ks++) {
                const int ksg = ch * 4 + ks;
                const uint32_t lx = (uint32_t)(((lane ^ (ks << 2)) ^ hswz) * 4);
                uint4 a0, a1;
                {
                    uint32_t base0 = ab + (uint32_t)((mtg0 * 4 + ks) * 512) + lx;
                    a0.x = lds32(base0);
                    a0.y = lds32(base0 + 128);
                    a0.z = lds32(base0 + 256);
                    a0.w = lds32(base0 + 384);
                    uint32_t base1 = base0 + 2048;   // next mt (same hi bit)
                    a1.x = lds32(base1);
                    a1.y = lds32(base1 + 128);
                    a1.z = lds32(base1 + 256);
                    a1.w = lds32(base1 + 384);
                }
                uint2 bfr[8];
                #pragma unroll
                for (int nt = 0; nt < 8; nt++)
                    bfr[nt] = lds64(bb + (uint32_t)((((ng * 8 + nt) * 16 + ksg) * 32
                                                    + lane) * 8));
                #pragma unroll
                for (int nt = 0; nt < 8; nt++) {
                    mma_f16(acc[0][nt], a0, bfr[nt]);
                    mma_f16(acc[1][nt], a1, bfr[nt]);
                }
            }
        }

        // ---- epilogue on last chunk of tile (v4, contiguous 16 cols) -----
        if (ch == 3) {
            const long mw = m0 + (long)(w & 3) * 32;
            const int  cb = h * N_HALF + ng * 64 + tig * 16;  // 16 contiguous cols
            #pragma unroll
            for (int mt = 0; mt < 2; mt++) {
                long r0 = mw + mt * 16 + g;
                long r1 = r0 + 8;
                if (r0 < NROWS_T) {
                    float* d0 = Y + r0 * D_DIM + cb;
                    #pragma unroll
                    for (int jj = 0; jj < 4; jj++)
                        stg128_cs(d0 + jj * 4,
                                  acc[mt][2 * jj][0], acc[mt][2 * jj][1],
                                  acc[mt][2 * jj + 1][0], acc[mt][2 * jj + 1][1]);
                }
                if (r1 < NROWS_T) {
                    float* d1 = Y + r1 * D_DIM + cb;
                    #pragma unroll
                    for (int jj = 0; jj < 4; jj++)
                        stg128_cs(d1 + jj * 4,
                                  acc[mt][2 * jj][2], acc[mt][2 * jj][3],
                                  acc[mt][2 * jj + 1][2], acc[mt][2 * jj + 1][3]);
                }
                #pragma unroll
                for (int nt = 0; nt < 8; nt++)
                    #pragma unroll
                    for (int q = 0; q < 4; q++) acc[mt][nt][q] = 0.0f;
            }
        }

        // ---- store prefetched chunk into other buffer --------------------
        if (cg + 1 < nchunks) {
            uint32_t ab = sb + SB_A + (uint32_t)((cg + 1) & 1) * A_STAGE_B;
            #pragma unroll
            for (int i = 0; i < 8; i++)
                sts64(ab + a_sts[i], u[i].x, u[i].y);
        }
    }
}

// ---------------------------------------------------------------------------
extern "C" void kernel_launch(void* const* d_in, const int* in_sizes, int n_in,
                              void* d_out, int out_size) {
    const float* X    = (const float*)d_in[0];
    const float* wv   = (const float*)d_in[1];
    const int*   rows = (const int*)d_in[2];
    const int*   cols = (const int*)d_in[3];
    const int nnz = in_sizes[1];

    cudaFuncSetAttribute(dag_gemm_kernel,
                         cudaFuncAttributeMaxDynamicSharedMemorySize, SMEM_TOTAL);
    dag_gemm_kernel<<<NCTA, NTHREADS, SMEM_TOTAL>>>(X, wv, rows, cols, nnz,
                                                    (float*)d_out);
}